// round 10
// baseline (speedup 1.0000x reference)
#include <cuda_runtime.h>
#include <cuda_fp16.h>
#include <cstdint>
#include <math.h>

// Problem constants
#define LL 1024
#define BB 2
#define FF 1024
#define HH 2048
#define NN 16
#define RR 64
#define KK 4
#define MROWS (LL*BB)        // 2048
#define PROJC (RR + 2*NN)    // 96

typedef __half h16;

// ---------------- scratch (device globals: allocation-free) ----------------
__device__ h16 g_xh [(size_t)MROWS * FF];
__device__ h16 g_Win[(size_t)(2*HH) * FF];      // [4096][1024] K-major
__device__ h16 g_xs [(size_t)MROWS * HH];
__device__ h16 g_Wc [(size_t)HH * (KK*1024)];   // [2048][4096]
__device__ h16 g_uh [(size_t)MROWS * HH];
__device__ h16 g_Ws [(size_t)128 * HH];         // [128 pad][2048]
__device__ h16 g_dth[(size_t)MROWS * RR];
__device__ h16 g_Wd [(size_t)HH * RR];          // [2048][64]
__device__ h16 g_zh [(size_t)MROWS * HH];
__device__ h16 g_Wo [(size_t)FF * HH];          // [1024][2048]
// fp32 intermediates for the scan
__device__ float g_res  [(size_t)MROWS * HH];
__device__ float g_u    [(size_t)MROWS * HH];
__device__ float g_proj [(size_t)MROWS * PROJC];
__device__ float g_delta[(size_t)MROWS * HH];

// ---------------- tiling ----------------------------------------------------
#define BM 128
#define BN 128
#define BK 32
#define ROW_B   80                        // 32 halves (64B) + 16B pad
#define ARR_B   (128 * ROW_B)             // 10240 B per operand tile
#define STAGE_B (2 * ARR_B)               // A + B = 20480 B
#define NSTAGE  4
#define SMEM_TOTAL (NSTAGE * STAGE_B)     // 81920 B

__device__ __forceinline__ float sigmoid_f(float x) {
    return 1.f / (1.f + __expf(-x));
}
__device__ __forceinline__ void mma_f16(float* d, const unsigned* a, const unsigned* b) {
    asm volatile(
        "mma.sync.aligned.m16n8k16.row.col.f32.f16.f16.f32 "
        "{%0,%1,%2,%3}, {%4,%5,%6,%7}, {%8,%9}, {%0,%1,%2,%3};\n"
        : "+f"(d[0]), "+f"(d[1]), "+f"(d[2]), "+f"(d[3])
        : "r"(a[0]), "r"(a[1]), "r"(a[2]), "r"(a[3]), "r"(b[0]), "r"(b[1]));
}
__device__ __forceinline__ void ldm_x4(unsigned* r, unsigned saddr) {
    asm volatile("ldmatrix.sync.aligned.m8n8.x4.shared.b16 {%0,%1,%2,%3}, [%4];"
        : "=r"(r[0]), "=r"(r[1]), "=r"(r[2]), "=r"(r[3]) : "r"(saddr));
}
__device__ __forceinline__ void cp16(void* smem_dst, const void* gsrc, bool valid) {
    unsigned s = (unsigned)__cvta_generic_to_shared(smem_dst);
    int sz = valid ? 16 : 0;
    asm volatile("cp.async.cg.shared.global [%0], [%1], 16, %2;\n"
                 :: "r"(s), "l"(gsrc), "r"(sz));
}
#define CP_COMMIT() asm volatile("cp.async.commit_group;\n")
#define CP_WAIT(n)  asm volatile("cp.async.wait_group %0;\n" :: "n"(n))

// ---------------- pre-passes -------------------------------------------------
__global__ void tohalf_k(const float* __restrict__ in, h16* __restrict__ o, int n)
{
    int i = blockIdx.x * blockDim.x + threadIdx.x;
    if (i < n) o[i] = __float2half_rn(in[i]);
}

// in [Kd][Nd] fp32 -> out [Npad][Kd] fp16 (rows >= Nd zero)
__device__ __forceinline__ void tr_body(const float* __restrict__ in,
                                        h16* __restrict__ o,
                                        int Kd, int Nd, int Npad,
                                        int k0, int n0)
{
    __shared__ float tile[32][33];
    for (int i = threadIdx.y; i < 32; i += 8) {
        int k = k0 + i, n = n0 + threadIdx.x;
        tile[i][threadIdx.x] = (k < Kd && n < Nd) ? in[(size_t)k * Nd + n] : 0.f;
    }
    __syncthreads();
    for (int i = threadIdx.y; i < 32; i += 8) {
        int n = n0 + i, k = k0 + threadIdx.x;
        if (n < Npad && k < Kd)
            o[(size_t)n * Kd + k] = __float2half_rn(tile[threadIdx.x][i]);
    }
}

__global__ void trhalf_k(const float* __restrict__ in, h16* __restrict__ o,
                         int Kd, int Nd, int Npad)
{
    tr_body(in, o, Kd, Nd, Npad, blockIdx.x * 32, blockIdx.y * 32);
}

// fused transpose of W_ssm, W_dt, W_out (blocks: 256 + 128 + 2048)
__global__ void tr3_k(const float* __restrict__ Ws_in, h16* __restrict__ Ws_o,
                      const float* __restrict__ Wd_in, h16* __restrict__ Wd_o,
                      const float* __restrict__ Wo_in, h16* __restrict__ Wo_o)
{
    int bid = blockIdx.x;
    if (bid < 256) {            // W_ssm: Kd=HH, Nd=96, Npad=128 -> 64 x 4 blocks
        int kb = bid & 63, nb = bid >> 6;
        tr_body(Ws_in, Ws_o, HH, PROJC, 128, kb * 32, nb * 32);
    } else if (bid < 384) {     // W_dt: Kd=64, Nd=HH -> 2 x 64 blocks
        int b2 = bid - 256;
        int kb = b2 & 1, nb = b2 >> 1;
        tr_body(Wd_in, Wd_o, RR, HH, HH, kb * 32, nb * 32);
    } else {                    // W_out: Kd=HH, Nd=FF -> 64 x 32 blocks
        int b2 = bid - 384;
        int kb = b2 & 63, nb = b2 >> 6;
        tr_body(Wo_in, Wo_o, HH, FF, FF, kb * 32, nb * 32);
    }
}

// ============ fp16 tensor GEMM: 128x128xK, 256 thr, 8 warps ================
// C = A[M,K] @ B[N,K]^T, fp32 accum.
// EPI 0: GEMM1  (c<HH -> fp16 Ch; else Cf = res fp32)
// EPI 1: conv   (silu(v+bias) -> Cf fp32 + fp16 Ch)
// EPI 2: proj   (c<96 -> Cf[96]; 32<=c<96 -> fp16 dt at col c-32)
// EPI 3: delta  (softplus(v+bias) -> Cf)
// EPI 4: out    (Cf plain)
template<int EPI, int CONV>
__global__ __launch_bounds__(256, 2)
void tc_gemm(const h16* __restrict__ A, int lda,
             const h16* __restrict__ B, int ldb,
             float* __restrict__ Cf, h16* __restrict__ Ch,
             int Nn, int Kk, const float* __restrict__ bias)
{
    extern __shared__ __align__(16) char smem[];
    const unsigned smb = (unsigned)__cvta_generic_to_shared(smem);

    const int tid  = threadIdx.x;
    const int col0 = blockIdx.x * BN;
    const int row0 = blockIdx.y * BM;
    const int grp  = CONV ? (col0 >> 10) : 0;
    const int warp = tid >> 5;
    const int lane = tid & 31;
    const int gid  = lane >> 2;        // 0..7
    const int tig  = lane & 3;         // 0..3
    const int wm0  = (warp & 3) * 32;
    const int wn0  = (warp >> 2) * 64;
    const int sel  = lane >> 3;        // 0..3 (ldmatrix quadrant)
    const int lr   = lane & 7;         // 0..7 (ldmatrix row)

    auto ld_tile = [&](int kt, int stage) {
        char* base = smem + stage * STAGE_B;
#pragma unroll
        for (int i = 0; i < 2; i++) {
            int q = tid + i * 256;
            int m = q >> 2, j = (q & 3) * 8;
            char* dst = base + m * ROW_B + j * 2;
            const h16* src;
            bool valid = true;
            if (CONV) {
                int tap = kt >> 10, ci0 = kt & 1023, shift = 2 * (3 - tap);
                int rs = row0 + m - shift;
                valid = rs >= 0;
                src = A + (size_t)(valid ? rs : 0) * lda + grp * 1024 + ci0 + j;
            } else {
                src = A + (size_t)(row0 + m) * lda + kt + j;
            }
            cp16(dst, src, valid);
        }
#pragma unroll
        for (int i = 0; i < 2; i++) {
            int q = tid + i * 256;
            int n = q >> 2, j = (q & 3) * 8;
            cp16(base + ARR_B + n * ROW_B + j * 2,
                 B + (size_t)(col0 + n) * ldb + kt + j, true);
        }
        CP_COMMIT();
    };

    float acc[2][8][4];
#pragma unroll
    for (int mt = 0; mt < 2; mt++)
#pragma unroll
        for (int nt = 0; nt < 8; nt++)
#pragma unroll
            for (int q = 0; q < 4; q++) acc[mt][nt][q] = 0.f;

    const int T = Kk / BK;
    // prologue: NSTAGE-1 committed groups (empty commits keep counting valid)
#pragma unroll
    for (int s = 0; s < NSTAGE - 1; s++) {
        if (s < T) ld_tile(s * BK, s);
        else       CP_COMMIT();
    }

    for (int t = 0; t < T; t++) {
        const int stage = t % NSTAGE;
        CP_WAIT(NSTAGE - 2);
        __syncthreads();
        // overwrites stage (t-1)%NSTAGE — all warps finished it before this sync
        if (t + NSTAGE - 1 < T) ld_tile((t + NSTAGE - 1) * BK, (t + NSTAGE - 1) % NSTAGE);
        else                    CP_COMMIT();

        const unsigned Abase = smb + stage * STAGE_B;
        const unsigned Bbase = Abase + ARR_B;

#pragma unroll
        for (int c = 0; c < 2; c++) {             // two k16 chunks
            unsigned a[2][4], b[8][2];
#pragma unroll
            for (int mt = 0; mt < 2; mt++) {
                int row  = wm0 + mt * 16 + ((sel & 1) << 3) + lr;
                int wcol = c * 8 + ((sel >> 1) << 2);
                ldm_x4(a[mt], Abase + row * ROW_B + wcol * 4);
            }
#pragma unroll
            for (int pr = 0; pr < 4; pr++) {      // pairs of n-tiles
                unsigned r4[4];
                int row  = wn0 + pr * 16 + ((sel >> 1) << 3) + lr;
                int wcol = c * 8 + ((sel & 1) << 2);
                ldm_x4(r4, Bbase + row * ROW_B + wcol * 4);
                b[pr * 2][0]     = r4[0]; b[pr * 2][1]     = r4[1];
                b[pr * 2 + 1][0] = r4[2]; b[pr * 2 + 1][1] = r4[3];
            }
#pragma unroll
            for (int mt = 0; mt < 2; mt++)
#pragma unroll
                for (int nt = 0; nt < 8; nt++)
                    mma_f16(acc[mt][nt], a[mt], b[nt]);
        }
    }

    auto epi_store = [&](int r, int c, float v) {
        if (EPI == 0) {
            if (c < HH) Ch[(size_t)r * HH + c] = __float2half_rn(v);
            else        Cf[(size_t)r * HH + (c - HH)] = v;
        } else if (EPI == 1) {
            v += bias[c]; v = v * sigmoid_f(v);
            Cf[(size_t)r * HH + c] = v;
            Ch[(size_t)r * HH + c] = __float2half_rn(v);
        } else if (EPI == 2) {
            if (c < PROJC) {
                Cf[(size_t)r * PROJC + c] = v;
                if (c >= 2 * NN)
                    Ch[(size_t)r * RR + (c - 2 * NN)] = __float2half_rn(v);
            }
        } else if (EPI == 3) {
            v += bias[c];
            v = (v > 20.f) ? v : log1pf(expf(v));
            Cf[(size_t)r * HH + c] = v;
        } else {
            Cf[(size_t)r * FF + c] = v;
        }
    };

#pragma unroll
    for (int mt = 0; mt < 2; mt++) {
        int r = row0 + wm0 + mt * 16 + gid;
#pragma unroll
        for (int nt = 0; nt < 8; nt++) {
            int c = col0 + wn0 + nt * 8 + tig * 2;
            epi_store(r,     c,     acc[mt][nt][0]);
            epi_store(r,     c + 1, acc[mt][nt][1]);
            epi_store(r + 8, c,     acc[mt][nt][2]);
            epi_store(r + 8, c + 1, acc[mt][nt][3]);
        }
    }
}

// ---------------- selective scan + fused z = y * silu(res) ----------------
__global__ __launch_bounds__(256)
void scan_k(const float* __restrict__ delta, const float* __restrict__ u,
            const float* __restrict__ proj, const float* __restrict__ A_log,
            const float* __restrict__ D, const float* __restrict__ res,
            h16* __restrict__ zh)
{
    const int gtid = blockIdx.x * blockDim.x + threadIdx.x;
    const int warp = gtid >> 5;
    const int lane = threadIdx.x & 31;
    const int sub  = lane >> 4;
    const int n    = lane & 15;
    const int c    = warp * 2 + sub;
    const int hi   = c >> 1;
    const int b    = c & 1;

    const float A  = -expf(A_log[hi * NN + n]);
    const float Dh = D[hi];
    float s = 0.f;

    for (int t = 0; t < LL; t++) {
        const int r = t * BB + b;
        float dt = __ldg(&delta[(size_t)r * HH + hi]);
        dt = fminf(fmaxf(dt, 0.001f), 0.1f);
        const float uu = __ldg(&u[(size_t)r * HH + hi]);
        const float Bn = __ldg(&proj[(size_t)r * PROJC + n]);
        const float Cn = __ldg(&proj[(size_t)r * PROJC + NN + n]);

        s = __expf(dt * A) * s + (dt * uu) * Bn;

        float p = Cn * s;
        p += __shfl_xor_sync(0xffffffffu, p, 1);
        p += __shfl_xor_sync(0xffffffffu, p, 2);
        p += __shfl_xor_sync(0xffffffffu, p, 4);
        p += __shfl_xor_sync(0xffffffffu, p, 8);

        if (n == 0) {
            const float yv = p + uu * Dh;
            const float rv = __ldg(&res[(size_t)r * HH + hi]);
            zh[(size_t)r * HH + hi] = __float2half_rn(yv * (rv * sigmoid_f(rv)));
        }
    }
}

// ---------------- launch ---------------------------------------------------
extern "C" void kernel_launch(void* const* d_in, const int* in_sizes, int n_in,
                              void* d_out, int out_size)
{
    const float* x      = (const float*)d_in[0];
    const float* W_in   = (const float*)d_in[1];
    const float* W_conv = (const float*)d_in[2];
    const float* b_conv = (const float*)d_in[3];
    const float* A_log  = (const float*)d_in[4];
    const float* D      = (const float*)d_in[5];
    const float* W_ssm  = (const float*)d_in[6];
    const float* W_dt   = (const float*)d_in[7];
    const float* b_dt   = (const float*)d_in[8];
    const float* W_out  = (const float*)d_in[9];
    float* out = (float*)d_out;

    void* p;
#define SYM(v, s) cudaGetSymbolAddress(&p, s); auto* v = decltype(&s[0])(p)
    SYM(xh, g_xh);   SYM(Win, g_Win);
    SYM(xs, g_xs);   SYM(Wc, g_Wc);
    SYM(uh, g_uh);   SYM(Ws, g_Ws);
    SYM(dth, g_dth); SYM(Wd, g_Wd);
    SYM(zh, g_zh);   SYM(Wo, g_Wo);
    SYM(resb, g_res); SYM(ub, g_u); SYM(pb, g_proj); SYM(db, g_delta);
#undef SYM

    cudaFuncSetAttribute(tc_gemm<0,0>, cudaFuncAttributeMaxDynamicSharedMemorySize, SMEM_TOTAL);
    cudaFuncSetAttribute(tc_gemm<1,1>, cudaFuncAttributeMaxDynamicSharedMemorySize, SMEM_TOTAL);
    cudaFuncSetAttribute(tc_gemm<2,0>, cudaFuncAttributeMaxDynamicSharedMemorySize, SMEM_TOTAL);
    cudaFuncSetAttribute(tc_gemm<3,0>, cudaFuncAttributeMaxDynamicSharedMemorySize, SMEM_TOTAL);
    cudaFuncSetAttribute(tc_gemm<4,0>, cudaFuncAttributeMaxDynamicSharedMemorySize, SMEM_TOTAL);

    dim3 blk(256);
    dim3 tblk(32, 8);

    // launches 1-4: conversions (so launch #6 = conv GEMM for ncu capture)
    {
        int n = MROWS * FF;
        tohalf_k<<<(n + 255) / 256, blk>>>(x, xh, n);                       // 1
    }
    trhalf_k<<<dim3(FF / 32, (2 * HH) / 32), tblk>>>(W_in, Win, FF, 2 * HH, 2 * HH); // 2
    trhalf_k<<<dim3((KK * 1024) / 32, HH / 32), tblk>>>(W_conv, Wc, KK * 1024, HH, HH); // 3
    tr3_k<<<256 + 128 + 2048, tblk>>>(W_ssm, Ws, W_dt, Wd, W_out, Wo);      // 4

    // 5) h = x @ W_in : xs half -> fp16 g_xs, res half -> fp32 g_res
    tc_gemm<0, 0><<<dim3(2 * HH / BN, MROWS / BM), blk, SMEM_TOTAL>>>(
        xh, FF, Win, FF, resb, xs, 2 * HH, FF, nullptr);

    // 6) u = silu(conv(xs) + b_conv) -> fp32 g_u + fp16 g_uh   [ncu capture]
    tc_gemm<1, 1><<<dim3(HH / BN, MROWS / BM), blk, SMEM_TOTAL>>>(
        xs, HH, Wc, KK * 1024, ub, uh, HH, KK * 1024, b_conv);

    // 7) proj = u @ W_ssm -> fp32 g_proj; dt cols -> fp16 g_dth
    tc_gemm<2, 0><<<dim3(1, MROWS / BM), blk, SMEM_TOTAL>>>(
        uh, HH, Ws, HH, pb, dth, PROJC, HH, nullptr);

    // 8) delta = softplus(dt @ W_dt + b_dt) -> fp32 g_delta
    tc_gemm<3, 0><<<dim3(HH / BN, MROWS / BM), blk, SMEM_TOTAL>>>(
        dth, RR, Wd, RR, db, nullptr, HH, RR, b_dt);

    // 9) selective scan + z = y * silu(res) -> fp16 g_zh
    scan_k<<<BB * HH * NN / 256, blk>>>(db, ub, pb, A_log, D, resb, zh);

    // 10) out = z @ W_out -> fp32 out
    tc_gemm<4, 0><<<dim3(FF / BN, MROWS / BM), blk, SMEM_TOTAL>>>(
        zh, HH, Wo, HH, out, nullptr, FF, HH, nullptr);
}

// round 11
// speedup vs baseline: 1.0630x; 1.0630x over previous
#include <cuda_runtime.h>
#include <cuda_fp16.h>
#include <cstdint>
#include <math.h>

// Problem constants
#define LL 1024
#define BB 2
#define FF 1024
#define HH 2048
#define NN 16
#define RR 64
#define KK 4
#define MROWS (LL*BB)        // 2048
#define PROJC (RR + 2*NN)    // 96

typedef __half h16;

// ---------------- scratch (device globals: allocation-free) ----------------
__device__ h16 g_xh [(size_t)MROWS * FF];
__device__ h16 g_Win[(size_t)(2*HH) * FF];      // [4096][1024] K-major
__device__ h16 g_xs [(size_t)MROWS * HH];
__device__ h16 g_Wc [(size_t)HH * (KK*1024)];   // [2048][4096]
__device__ h16 g_uh [(size_t)MROWS * HH];
__device__ h16 g_resh[(size_t)MROWS * HH];
__device__ h16 g_Ws [(size_t)128 * HH];         // [128 pad][2048]
__device__ h16 g_dth[(size_t)MROWS * RR];
__device__ h16 g_Wd [(size_t)HH * RR];          // [2048][64]
__device__ h16 g_zh [(size_t)MROWS * HH];
__device__ h16 g_Wo [(size_t)FF * HH];          // [1024][2048]
// fp32 intermediates for the scan
__device__ float g_proj [(size_t)MROWS * PROJC];
__device__ float g_delta[(size_t)MROWS * HH];

// ---------------- tiling ----------------------------------------------------
#define BM 128
#define BN 128
#define BK 32
#define ROW_B   80                        // 32 halves (64B) + 16B pad
#define ARR_B   (128 * ROW_B)             // 10240 B per operand tile
#define STAGE_B (2 * ARR_B)               // A + B = 20480 B
#define NSTAGE  3
#define SMEM_TOTAL (NSTAGE * STAGE_B)     // 61440 B

__device__ __forceinline__ float sigmoid_f(float x) {
    return 1.f / (1.f + __expf(-x));
}
__device__ __forceinline__ void mma_f16(float* d, const unsigned* a, const unsigned* b) {
    asm volatile(
        "mma.sync.aligned.m16n8k16.row.col.f32.f16.f16.f32 "
        "{%0,%1,%2,%3}, {%4,%5,%6,%7}, {%8,%9}, {%0,%1,%2,%3};\n"
        : "+f"(d[0]), "+f"(d[1]), "+f"(d[2]), "+f"(d[3])
        : "r"(a[0]), "r"(a[1]), "r"(a[2]), "r"(a[3]), "r"(b[0]), "r"(b[1]));
}
__device__ __forceinline__ void ldm_x4(unsigned* r, unsigned saddr) {
    asm volatile("ldmatrix.sync.aligned.m8n8.x4.shared.b16 {%0,%1,%2,%3}, [%4];"
        : "=r"(r[0]), "=r"(r[1]), "=r"(r[2]), "=r"(r[3]) : "r"(saddr));
}
__device__ __forceinline__ void cp16(void* smem_dst, const void* gsrc, bool valid) {
    unsigned s = (unsigned)__cvta_generic_to_shared(smem_dst);
    int sz = valid ? 16 : 0;
    asm volatile("cp.async.cg.shared.global [%0], [%1], 16, %2;\n"
                 :: "r"(s), "l"(gsrc), "r"(sz));
}
#define CP_COMMIT() asm volatile("cp.async.commit_group;\n")
#define CP_WAIT(n)  asm volatile("cp.async.wait_group %0;\n" :: "n"(n))

// ---------------- pre-passes -------------------------------------------------
// in [Kd][Nd] fp32 -> out [Npad][Kd] fp16 (rows >= Nd zero)
__device__ __forceinline__ void tr_body(const float* __restrict__ in,
                                        h16* __restrict__ o,
                                        int Kd, int Nd, int Npad,
                                        int k0, int n0)
{
    __shared__ float tile[32][33];
    for (int i = threadIdx.y; i < 32; i += 8) {
        int k = k0 + i, n = n0 + threadIdx.x;
        tile[i][threadIdx.x] = (k < Kd && n < Nd) ? in[(size_t)k * Nd + n] : 0.f;
    }
    __syncthreads();
    for (int i = threadIdx.y; i < 32; i += 8) {
        int n = n0 + i, k = k0 + threadIdx.x;
        if (n < Npad && k < Kd)
            o[(size_t)n * Kd + k] = __float2half_rn(tile[threadIdx.x][i]);
    }
}

// launch 1: blocks [0,8192): tohalf(x); blocks [8192, 16384): trhalf(W_conv)
__global__ void cvt1_k(const float* __restrict__ x, h16* __restrict__ xh,
                       const float* __restrict__ Wc_in, h16* __restrict__ Wc_o)
{
    int bid = blockIdx.x;
    int t = threadIdx.y * 32 + threadIdx.x;
    if (bid < 8192) {
        int i = bid * 256 + t;                   // MROWS*FF = 2M elements
        if (i < MROWS * FF) xh[i] = __float2half_rn(x[i]);
    } else {
        int b2 = bid - 8192;                     // 128 x 64 blocks
        int kb = b2 & 127, nb = b2 >> 7;
        tr_body(Wc_in, Wc_o, KK * 1024, HH, HH, kb * 32, nb * 32);
    }
}

__global__ void trhalf_k(const float* __restrict__ in, h16* __restrict__ o,
                         int Kd, int Nd, int Npad)
{
    tr_body(in, o, Kd, Nd, Npad, blockIdx.x * 32, blockIdx.y * 32);
}

// fused transpose of W_ssm, W_dt, W_out (blocks: 256 + 128 + 2048)
__global__ void tr3_k(const float* __restrict__ Ws_in, h16* __restrict__ Ws_o,
                      const float* __restrict__ Wd_in, h16* __restrict__ Wd_o,
                      const float* __restrict__ Wo_in, h16* __restrict__ Wo_o)
{
    int bid = blockIdx.x;
    if (bid < 256) {            // W_ssm: Kd=HH, Nd=96, Npad=128 -> 64 x 4
        int kb = bid & 63, nb = bid >> 6;
        tr_body(Ws_in, Ws_o, HH, PROJC, 128, kb * 32, nb * 32);
    } else if (bid < 384) {     // W_dt: Kd=64, Nd=HH -> 2 x 64
        int b2 = bid - 256;
        int kb = b2 & 1, nb = b2 >> 1;
        tr_body(Wd_in, Wd_o, RR, HH, HH, kb * 32, nb * 32);
    } else {                    // W_out: Kd=HH, Nd=FF -> 64 x 32
        int b2 = bid - 384;
        int kb = b2 & 63, nb = b2 >> 6;
        tr_body(Wo_in, Wo_o, HH, FF, FF, kb * 32, nb * 32);
    }
}

// ============ fp16 tensor GEMM: 128x128xK, 256 thr, 8 warps ================
// C = A[M,K] @ B[N,K]^T, fp32 accum.
// EPI 0: GEMM1  (c<HH -> fp16 Ch=xs; else fp16 Ch2=res at col c-HH)
// EPI 1: conv   (silu(v+bias) -> fp16 Ch=u)
// EPI 2: proj   (c<96 -> Cf[96]; 32<=c<96 -> fp16 Ch=dt at col c-32)
// EPI 3: delta  (softplus(v+bias) -> Cf fp32)
// EPI 4: out    (Cf plain fp32)
template<int EPI, int CONV>
__global__ __launch_bounds__(256, 2)
void tc_gemm(const h16* __restrict__ A, int lda,
             const h16* __restrict__ B, int ldb,
             float* __restrict__ Cf, h16* __restrict__ Ch, h16* __restrict__ Ch2,
             int Nn, int Kk, const float* __restrict__ bias)
{
    extern __shared__ __align__(16) char smem[];
    const unsigned smb = (unsigned)__cvta_generic_to_shared(smem);

    const int tid  = threadIdx.x;
    const int col0 = blockIdx.x * BN;
    const int row0 = blockIdx.y * BM;
    const int grp  = CONV ? (col0 >> 10) : 0;
    const int warp = tid >> 5;
    const int lane = tid & 31;
    const int gid  = lane >> 2;        // 0..7
    const int tig  = lane & 3;         // 0..3
    const int wm0  = (warp & 3) * 32;
    const int wn0  = (warp >> 2) * 64;
    const int sel  = lane >> 3;        // 0..3 (ldmatrix quadrant)
    const int lr   = lane & 7;         // 0..7 (ldmatrix row)

    auto ld_tile = [&](int kt, int stage) {
        char* base = smem + stage * STAGE_B;
#pragma unroll
        for (int i = 0; i < 2; i++) {
            int q = tid + i * 256;
            int m = q >> 2, j = (q & 3) * 8;
            char* dst = base + m * ROW_B + j * 2;
            const h16* src;
            bool valid = true;
            if (CONV) {
                int tap = kt >> 10, ci0 = kt & 1023, shift = 2 * (3 - tap);
                int rs = row0 + m - shift;
                valid = rs >= 0;
                src = A + (size_t)(valid ? rs : 0) * lda + grp * 1024 + ci0 + j;
            } else {
                src = A + (size_t)(row0 + m) * lda + kt + j;
            }
            cp16(dst, src, valid);
        }
#pragma unroll
        for (int i = 0; i < 2; i++) {
            int q = tid + i * 256;
            int n = q >> 2, j = (q & 3) * 8;
            cp16(base + ARR_B + n * ROW_B + j * 2,
                 B + (size_t)(col0 + n) * ldb + kt + j, true);
        }
        CP_COMMIT();
    };

    float acc[2][8][4];
#pragma unroll
    for (int mt = 0; mt < 2; mt++)
#pragma unroll
        for (int nt = 0; nt < 8; nt++)
#pragma unroll
            for (int q = 0; q < 4; q++) acc[mt][nt][q] = 0.f;

    const int T = Kk / BK;
    ld_tile(0, 0);
    if (T > 1) ld_tile(BK, 1);

    for (int t = 0; t < T; t++) {
        const int stage = t % NSTAGE;
        if (t + 1 < T) CP_WAIT(1); else CP_WAIT(0);
        __syncthreads();
        if (t + 2 < T) ld_tile((t + 2) * BK, (t + 2) % NSTAGE);

        const unsigned Abase = smb + stage * STAGE_B;
        const unsigned Bbase = Abase + ARR_B;

#pragma unroll
        for (int c = 0; c < 2; c++) {             // two k16 chunks
            unsigned a[2][4], b[8][2];
#pragma unroll
            for (int mt = 0; mt < 2; mt++) {
                int row  = wm0 + mt * 16 + ((sel & 1) << 3) + lr;
                int wcol = c * 8 + ((sel >> 1) << 2);
                ldm_x4(a[mt], Abase + row * ROW_B + wcol * 4);
            }
#pragma unroll
            for (int pr = 0; pr < 4; pr++) {      // pairs of n-tiles
                unsigned r4[4];
                int row  = wn0 + pr * 16 + ((sel >> 1) << 3) + lr;
                int wcol = c * 8 + ((sel & 1) << 2);
                ldm_x4(r4, Bbase + row * ROW_B + wcol * 4);
                b[pr * 2][0]     = r4[0]; b[pr * 2][1]     = r4[1];
                b[pr * 2 + 1][0] = r4[2]; b[pr * 2 + 1][1] = r4[3];
            }
#pragma unroll
            for (int mt = 0; mt < 2; mt++)
#pragma unroll
                for (int nt = 0; nt < 8; nt++)
                    mma_f16(acc[mt][nt], a[mt], b[nt]);
        }
        __syncthreads();
    }

    auto epi_store = [&](int r, int c, float v) {
        if (EPI == 0) {
            if (c < HH) Ch[(size_t)r * HH + c] = __float2half_rn(v);
            else        Ch2[(size_t)r * HH + (c - HH)] = __float2half_rn(v);
        } else if (EPI == 1) {
            v += bias[c]; v = v * sigmoid_f(v);
            Ch[(size_t)r * HH + c] = __float2half_rn(v);
        } else if (EPI == 2) {
            if (c < PROJC) {
                Cf[(size_t)r * PROJC + c] = v;
                if (c >= 2 * NN)
                    Ch[(size_t)r * RR + (c - 2 * NN)] = __float2half_rn(v);
            }
        } else if (EPI == 3) {
            v += bias[c];
            v = (v > 20.f) ? v : log1pf(expf(v));
            Cf[(size_t)r * HH + c] = v;
        } else {
            Cf[(size_t)r * FF + c] = v;
        }
    };

#pragma unroll
    for (int mt = 0; mt < 2; mt++) {
        int r = row0 + wm0 + mt * 16 + gid;
#pragma unroll
        for (int nt = 0; nt < 8; nt++) {
            int c = col0 + wn0 + nt * 8 + tig * 2;
            epi_store(r,     c,     acc[mt][nt][0]);
            epi_store(r,     c + 1, acc[mt][nt][1]);
            epi_store(r + 8, c,     acc[mt][nt][2]);
            epi_store(r + 8, c + 1, acc[mt][nt][3]);
        }
    }
}

// ---------------- selective scan + fused z = y * silu(res) ----------------
__global__ __launch_bounds__(256)
void scan_k(const float* __restrict__ delta, const h16* __restrict__ uh,
            const float* __restrict__ proj, const float* __restrict__ A_log,
            const float* __restrict__ D, const h16* __restrict__ resh,
            h16* __restrict__ zh)
{
    const int gtid = blockIdx.x * blockDim.x + threadIdx.x;
    const int warp = gtid >> 5;
    const int lane = threadIdx.x & 31;
    const int sub  = lane >> 4;
    const int n    = lane & 15;
    const int c    = warp * 2 + sub;
    const int hi   = c >> 1;
    const int b    = c & 1;

    const float A  = -expf(A_log[hi * NN + n]);
    const float Dh = D[hi];
    float s = 0.f;

    for (int t = 0; t < LL; t++) {
        const int r = t * BB + b;
        float dt = __ldg(&delta[(size_t)r * HH + hi]);
        dt = fminf(fmaxf(dt, 0.001f), 0.1f);
        const float uu = __half2float(__ldg(&uh[(size_t)r * HH + hi]));
        const float Bn = __ldg(&proj[(size_t)r * PROJC + n]);
        const float Cn = __ldg(&proj[(size_t)r * PROJC + NN + n]);

        s = __expf(dt * A) * s + (dt * uu) * Bn;

        float p = Cn * s;
        p += __shfl_xor_sync(0xffffffffu, p, 1);
        p += __shfl_xor_sync(0xffffffffu, p, 2);
        p += __shfl_xor_sync(0xffffffffu, p, 4);
        p += __shfl_xor_sync(0xffffffffu, p, 8);

        if (n == 0) {
            const float yv = p + uu * Dh;
            const float rv = __half2float(__ldg(&resh[(size_t)r * HH + hi]));
            zh[(size_t)r * HH + hi] = __float2half_rn(yv * (rv * sigmoid_f(rv)));
        }
    }
}

// ---------------- launch ---------------------------------------------------
extern "C" void kernel_launch(void* const* d_in, const int* in_sizes, int n_in,
                              void* d_out, int out_size)
{
    const float* x      = (const float*)d_in[0];
    const float* W_in   = (const float*)d_in[1];
    const float* W_conv = (const float*)d_in[2];
    const float* b_conv = (const float*)d_in[3];
    const float* A_log  = (const float*)d_in[4];
    const float* D      = (const float*)d_in[5];
    const float* W_ssm  = (const float*)d_in[6];
    const float* W_dt   = (const float*)d_in[7];
    const float* b_dt   = (const float*)d_in[8];
    const float* W_out  = (const float*)d_in[9];
    float* out = (float*)d_out;

    void* p;
#define SYM(v, s) cudaGetSymbolAddress(&p, s); auto* v = decltype(&s[0])(p)
    SYM(xh, g_xh);   SYM(Win, g_Win);
    SYM(xs, g_xs);   SYM(Wc, g_Wc);
    SYM(uh, g_uh);   SYM(resh, g_resh);
    SYM(Ws, g_Ws);
    SYM(dth, g_dth); SYM(Wd, g_Wd);
    SYM(zh, g_zh);   SYM(Wo, g_Wo);
    SYM(pb, g_proj); SYM(db, g_delta);
#undef SYM

    cudaFuncSetAttribute(tc_gemm<0,0>, cudaFuncAttributeMaxDynamicSharedMemorySize, SMEM_TOTAL);
    cudaFuncSetAttribute(tc_gemm<1,1>, cudaFuncAttributeMaxDynamicSharedMemorySize, SMEM_TOTAL);
    cudaFuncSetAttribute(tc_gemm<2,0>, cudaFuncAttributeMaxDynamicSharedMemorySize, SMEM_TOTAL);
    cudaFuncSetAttribute(tc_gemm<3,0>, cudaFuncAttributeMaxDynamicSharedMemorySize, SMEM_TOTAL);
    cudaFuncSetAttribute(tc_gemm<4,0>, cudaFuncAttributeMaxDynamicSharedMemorySize, SMEM_TOTAL);

    dim3 blk(256);
    dim3 tblk(32, 8);

    // 1) x -> fp16 AND W_conv transpose (fused)
    cvt1_k<<<8192 + 8192, tblk>>>(x, xh, W_conv, Wc);

    // 2) W_in transpose
    trhalf_k<<<dim3(FF / 32, (2 * HH) / 32), tblk>>>(W_in, Win, FF, 2 * HH, 2 * HH);

    // 3) h = x @ W_in : xs -> fp16 g_xs, res -> fp16 g_resh
    tc_gemm<0, 0><<<dim3(2 * HH / BN, MROWS / BM), blk, SMEM_TOTAL>>>(
        xh, FF, Win, FF, nullptr, xs, resh, 2 * HH, FF, nullptr);

    // 4) u = silu(conv(xs) + b_conv) -> fp16 g_uh   [ncu capture slot]
    tc_gemm<1, 1><<<dim3(HH / BN, MROWS / BM), blk, SMEM_TOTAL>>>(
        xs, HH, Wc, KK * 1024, nullptr, uh, nullptr, HH, KK * 1024, b_conv);

    // 5) transpose W_ssm / W_dt / W_out
    tr3_k<<<256 + 128 + 2048, tblk>>>(W_ssm, Ws, W_dt, Wd, W_out, Wo);

    // 6) proj = u @ W_ssm -> fp32 g_proj; dt cols -> fp16 g_dth
    tc_gemm<2, 0><<<dim3(1, MROWS / BM), blk, SMEM_TOTAL>>>(
        uh, HH, Ws, HH, pb, dth, nullptr, PROJC, HH, nullptr);

    // 7) delta = softplus(dt @ W_dt + b_dt) -> fp32 g_delta
    tc_gemm<3, 0><<<dim3(HH / BN, MROWS / BM), blk, SMEM_TOTAL>>>(
        dth, RR, Wd, RR, db, nullptr, nullptr, HH, RR, b_dt);

    // 8) selective scan + z = y * silu(res) -> fp16 g_zh
    scan_k<<<BB * HH * NN / 256, blk>>>(db, uh, pb, A_log, D, resh, zh);

    // 9) out = z @ W_out -> fp32 out
    tc_gemm<4, 0><<<dim3(FF / BN, MROWS / BM), blk, SMEM_TOTAL>>>(
        zh, HH, Wo, HH, out, nullptr, nullptr, FF, HH, nullptr);
}